// round 11
// baseline (speedup 1.0000x reference)
#include <cuda_runtime.h>
#include <cstdint>

#define N_NODES 50000
#define N_EDGES 800000
#define F_X 128
#define F_E 128
#define HIDDEN 512
#define F_OUT 128

// ---------------- scratch (static device globals; no runtime alloc) --------
__device__ float    g_agg[(size_t)N_NODES * F_E];              // 25.6 MB fp32
__device__ uint32_t g_A[(size_t)N_NODES * (F_E + F_X)];        // 51.2 MB tf32 [50000][256]
__device__ uint32_t g_h[(size_t)N_NODES * HIDDEN];             // 102.4 MB tf32 bits
__device__ uint32_t g_W1t[(size_t)HIDDEN * (F_E + F_X)];       // W1^T tf32 [512][256]
__device__ uint32_t g_W2t[(size_t)F_OUT * HIDDEN];             // W2^T tf32 [128][512]

__device__ __forceinline__ uint32_t f2tf32(float f) {
    uint32_t r; asm("cvt.rna.tf32.f32 %0, %1;" : "=r"(r) : "f"(f)); return r;
}
__device__ __forceinline__ uint32_t smem_u32(const void* p) {
    uint32_t a;
    asm("{ .reg .u64 t; cvta.to.shared.u64 t, %1; cvt.u32.u64 %0, t; }"
        : "=r"(a) : "l"(p));
    return a;
}

// ---------------------------------------------------------------------------
// scatter-add, one warp per edge, red.global.add.v4.f32
// ---------------------------------------------------------------------------
__global__ void __launch_bounds__(256) scatter_edges_kernel(
    const float4* __restrict__ edge_attr, const int* __restrict__ receivers)
{
    int gt = blockIdx.x * blockDim.x + threadIdx.x;
    int edge = gt >> 5;
    int lane = gt & 31;
    if (edge >= N_EDGES) return;

    int r = __ldg(receivers + edge);
    float4 v = edge_attr[(size_t)edge * 32 + lane];
    float* dst = g_agg + (size_t)r * F_E + lane * 4;
    asm volatile("red.global.add.v4.f32 [%0], {%1,%2,%3,%4};"
                 :: "l"(dst), "f"(v.x), "f"(v.y), "f"(v.z), "f"(v.w)
                 : "memory");
}

// ---------------------------------------------------------------------------
// fused prep — concat(g_agg|nodes)->g_A tf32, W1->W1t, W2->W2t
// ---------------------------------------------------------------------------
#define PREP_NC  (N_NODES * 64)                  // 3,200,000 float4 items
#define PREP_NW1 (HIDDEN * (F_E + F_X))          // 131,072
#define PREP_NW2 (F_OUT * HIDDEN)                // 65,536
#define PREP_TOTAL (PREP_NC + PREP_NW1 + PREP_NW2)

__global__ void __launch_bounds__(256) prep_kernel(
    const float4* __restrict__ nodes,
    const float* __restrict__ W1, const float* __restrict__ W2)
{
    int i = blockIdx.x * blockDim.x + threadIdx.x;
    if (i < PREP_NC) {
        int row = i >> 6, c4 = i & 63;
        float4 v = (c4 < 32)
            ? reinterpret_cast<const float4*>(g_agg)[(size_t)row * 32 + c4]
            : nodes[(size_t)row * 32 + (c4 - 32)];
        uint4 t;
        t.x = f2tf32(v.x); t.y = f2tf32(v.y);
        t.z = f2tf32(v.z); t.w = f2tf32(v.w);
        reinterpret_cast<uint4*>(g_A)[i] = t;
    } else if (i < PREP_NC + PREP_NW1) {
        int idx = i - PREP_NC;
        int n = idx >> 8, k = idx & 255;                 // K=256
        g_W1t[idx] = f2tf32(W1[(size_t)k * HIDDEN + n]);
    } else if (i < PREP_TOTAL) {
        int idx = i - PREP_NC - PREP_NW1;
        int n = idx >> 9, k = idx & 511;                 // K=512
        g_W2t[idx] = f2tf32(W2[(size_t)k * F_OUT + n]);
    }
}

// ---------------------------------------------------------------------------
// cp.async 3-stage pipelined tf32 mma GEMM, BK=32, single barrier per tile.
// L1=true : BM=128,BN=128; 8 warps 2m x 4n (warp 64x32). A=g_A K=256.
//           out = g_h (tf32 bits) with bias+ReLU.
// L1=false: BM=128,BN= 64; 8 warps 4m x 2n (warp 32x32). A=g_h K=512.
//           out = Cout fp32 with bias.  grid.x=2 -> 782 CTAs (tail fix).
// Stage: (128+BN) x 36 words; stride 36 -> frag bank = 4g+t4 (+const), CF.
// ---------------------------------------------------------------------------
template <bool L1>
__global__ void __launch_bounds__(256)
gemm_pipe_kernel(const uint32_t* __restrict__ Aglob,
                 const uint32_t* __restrict__ Wt,
                 const float* __restrict__ bias,
                 float* __restrict__ Cout)
{
    constexpr int K  = L1 ? (F_E + F_X) : HIDDEN;
    constexpr int N  = L1 ? HIDDEN : F_OUT;
    constexpr int BN = L1 ? 128 : 64;
    constexpr int MT = L1 ? 4 : 2;
    constexpr int M  = N_NODES;
    constexpr int NTILES = K / 32;
    constexpr int STW = (128 + BN) * 36;     // stage words
    constexpr int BCH = BN / 32;             // B chunks per thread (4 or 2)

    extern __shared__ uint32_t smem[];
    const uint32_t sbase = smem_u32(smem);

    const int tid  = threadIdx.x;
    const int lane = tid & 31;
    const int warp = tid >> 5;
    const int m0 = blockIdx.y * 128;
    const int n0 = blockIdx.x * BN;
    const int warp_m = L1 ? ((warp >> 2) * 64) : ((warp >> 1) * 32);
    const int warp_n = L1 ? ((warp & 3) * 32) : ((warp & 1) * 32);
    const int g  = lane >> 2;
    const int t4 = lane & 3;

    // staging: A 128x32 = 1024 float4 (4 chunks/thr); B BNx32 (BCH chunks/thr)
    int srow[4], sq[4], a_ok[4];
    #pragma unroll
    for (int i = 0; i < 4; ++i) {
        int e = tid + i * 256;
        srow[i] = e >> 3;
        sq[i]   = (e & 7) * 4;
        a_ok[i] = (m0 + srow[i]) < M ? 16 : 0;
    }

    float acc[MT][4][4];
    #pragma unroll
    for (int mt = 0; mt < MT; ++mt)
        #pragma unroll
        for (int nt = 0; nt < 4; ++nt)
            #pragma unroll
            for (int i = 0; i < 4; ++i) acc[mt][nt][i] = 0.f;

    auto issue = [&](int tile, int slot) {
        const int k0 = tile * 32;
        uint32_t ab = sbase + (slot * STW) * 4;
        uint32_t bb = ab + (128 * 36) * 4;
        #pragma unroll
        for (int i = 0; i < 4; ++i) {
            asm volatile("cp.async.cg.shared.global [%0], [%1], 16, %2;"
                :: "r"(ab + (srow[i] * 36 + sq[i]) * 4),
                   "l"(Aglob + (size_t)(m0 + srow[i]) * K + k0 + sq[i]),
                   "r"(a_ok[i]) : "memory");
        }
        #pragma unroll
        for (int i = 0; i < BCH; ++i) {
            asm volatile("cp.async.cg.shared.global [%0], [%1], 16;"
                :: "r"(bb + (srow[i] * 36 + sq[i]) * 4),
                   "l"(Wt + (size_t)(n0 + srow[i]) * K + k0 + sq[i])
                : "memory");
        }
    };

    issue(0, 0); asm volatile("cp.async.commit_group;" ::: "memory");
    issue(1, 1); asm volatile("cp.async.commit_group;" ::: "memory");

    for (int it = 0; it < NTILES; ++it) {
        asm volatile("cp.async.wait_group 1;" ::: "memory");
        __syncthreads();
        // Single barrier per tile: every warp passing it has finished
        // compute(it-1), so slot (it+2)%3 == (it-1)%3 is free to overwrite.
        if (it + 2 < NTILES) issue(it + 2, (it + 2) % 3);
        asm volatile("cp.async.commit_group;" ::: "memory");   // keep count exact

        const uint32_t* As = smem + (it % 3) * STW;
        const uint32_t* Bs = As + 128 * 36;

        #pragma unroll
        for (int ks = 0; ks < 4; ++ks) {
            const int kb = ks * 8;
            uint32_t a[MT][4], b[4][2];
            #pragma unroll
            for (int mt = 0; mt < MT; ++mt) {
                int mb = warp_m + mt * 16;
                a[mt][0] = As[(mb + g)     * 36 + kb + t4];
                a[mt][1] = As[(mb + g + 8) * 36 + kb + t4];
                a[mt][2] = As[(mb + g)     * 36 + kb + t4 + 4];
                a[mt][3] = As[(mb + g + 8) * 36 + kb + t4 + 4];
            }
            #pragma unroll
            for (int nt = 0; nt < 4; ++nt) {
                int nb = warp_n + nt * 8;
                b[nt][0] = Bs[(nb + g) * 36 + kb + t4];
                b[nt][1] = Bs[(nb + g) * 36 + kb + t4 + 4];
            }
            #pragma unroll
            for (int mt = 0; mt < MT; ++mt)
                #pragma unroll
                for (int nt = 0; nt < 4; ++nt)
                    asm volatile(
                        "mma.sync.aligned.m16n8k8.row.col.f32.tf32.tf32.f32 "
                        "{%0,%1,%2,%3}, {%4,%5,%6,%7}, {%8,%9}, {%0,%1,%2,%3};"
                        : "+f"(acc[mt][nt][0]), "+f"(acc[mt][nt][1]),
                          "+f"(acc[mt][nt][2]), "+f"(acc[mt][nt][3])
                        : "r"(a[mt][0]), "r"(a[mt][1]),
                          "r"(a[mt][2]), "r"(a[mt][3]),
                          "r"(b[nt][0]), "r"(b[nt][1]));
        }
    }

    // ---- epilogue ----
    #pragma unroll
    for (int mt = 0; mt < MT; ++mt) {
        #pragma unroll
        for (int nt = 0; nt < 4; ++nt) {
            int gc = n0 + warp_n + nt * 8 + t4 * 2;
            float2 bv = *reinterpret_cast<const float2*>(bias + gc);
            #pragma unroll
            for (int hh = 0; hh < 2; ++hh) {
                int gr = m0 + warp_m + mt * 16 + g + hh * 8;
                if (gr >= M) continue;
                float ox = acc[mt][nt][hh * 2 + 0] + bv.x;
                float oy = acc[mt][nt][hh * 2 + 1] + bv.y;
                if (L1) {
                    uint2 t;
                    t.x = f2tf32(fmaxf(ox, 0.f));
                    t.y = f2tf32(fmaxf(oy, 0.f));
                    *reinterpret_cast<uint2*>(g_h + (size_t)gr * N + gc) = t;
                } else {
                    float2 o = make_float2(ox, oy);
                    *reinterpret_cast<float2*>(Cout + (size_t)gr * N + gc) = o;
                }
            }
        }
    }
}

// ---------------------------------------------------------------------------
// order: memset(agg) -> scatter -> prep -> gemm1 -> gemm2
// Inputs: nodes, edge_attr, senders, receivers, W1, b1, W2, b2
// ---------------------------------------------------------------------------
extern "C" void kernel_launch(void* const* d_in, const int* in_sizes, int n_in,
                              void* d_out, int out_size)
{
    const float*  nodes     = (const float*)d_in[0];
    const float4* edge_attr = (const float4*)d_in[1];
    const int*    receivers = (const int*)d_in[3];
    const float*  W1        = (const float*)d_in[4];
    const float*  b1        = (const float*)d_in[5];
    const float*  W2        = (const float*)d_in[6];
    const float*  b2        = (const float*)d_in[7];
    float* out = (float*)d_out;

    uint32_t *w1t = nullptr, *w2t = nullptr, *gA = nullptr, *gh = nullptr;
    float* gagg = nullptr;
    cudaGetSymbolAddress((void**)&w1t,  g_W1t);
    cudaGetSymbolAddress((void**)&w2t,  g_W2t);
    cudaGetSymbolAddress((void**)&gA,   g_A);
    cudaGetSymbolAddress((void**)&gh,   g_h);
    cudaGetSymbolAddress((void**)&gagg, g_agg);

    constexpr int SMEM1 = 3 * (256 * 36) * 4;   // 110,592 B
    constexpr int SMEM2 = 3 * (192 * 36) * 4;   //  82,944 B

    static bool attr_set = false;
    if (!attr_set) {
        cudaFuncSetAttribute(gemm_pipe_kernel<true>,
                             cudaFuncAttributeMaxDynamicSharedMemorySize, SMEM1);
        cudaFuncSetAttribute(gemm_pipe_kernel<false>,
                             cudaFuncAttributeMaxDynamicSharedMemorySize, SMEM2);
        attr_set = true;
    }

    // 1) zero agg via memset node (graph-capturable, no kernel launch)
    cudaMemsetAsync(gagg, 0, (size_t)N_NODES * F_E * sizeof(float));

    // 2) scatter
    {
        long long total = (long long)N_EDGES * 32;
        int blocks = (int)((total + 255) / 256);
        scatter_edges_kernel<<<blocks, 256>>>(edge_attr, receivers);
    }
    // 3) prep
    prep_kernel<<<(PREP_TOTAL + 255) / 256, 256>>>(
        (const float4*)nodes, W1, W2);
    // 4) gemm1
    {
        dim3 grid(HIDDEN / 128, (N_NODES + 127) / 128);   // (4, 391)
        gemm_pipe_kernel<true><<<grid, 256, SMEM1>>>(gA, w1t, b1, nullptr);
    }
    // 5) gemm2 (BN=64 -> grid (2, 391) = 782 CTAs)
    {
        dim3 grid(F_OUT / 64, (N_NODES + 127) / 128);
        gemm_pipe_kernel<false><<<grid, 256, SMEM2>>>(gh, w2t, b2, out);
    }
}